// round 12
// baseline (speedup 1.0000x reference)
#include <cuda_runtime.h>
#include <cuda_fp16.h>
#include <cstdint>
#include <cstddef>

// Scratch: E = enc@W^T (2048x1024), D = dec@W^T + bias (512x1024)
__device__ float g_E[2048 * 1024];
__device__ float g_D[512 * 1024];

constexpr int KDIM = 512, NDIM = 1024;
constexpr int BM = 128, BN = 128, BK = 32;   // BK floats; 16 half2 k-rows
constexpr int NKT = KDIM / BK;               // 16 k-tiles
constexpr int STR = 136;                     // frag reads bank-conflict-free

__device__ __forceinline__ void mma_f16(float* c, const uint32_t* a, const uint32_t* b) {
    asm volatile(
        "mma.sync.aligned.m16n8k16.row.col.f32.f16.f16.f32 "
        "{%0,%1,%2,%3}, {%4,%5,%6,%7}, {%8,%9}, {%0,%1,%2,%3};\n"
        : "+f"(c[0]), "+f"(c[1]), "+f"(c[2]), "+f"(c[3])
        : "r"(a[0]), "r"(a[1]), "r"(a[2]), "r"(a[3]), "r"(b[0]), "r"(b[1]));
}

__device__ __forceinline__ uint32_t pack_h2(float x, float y) {
    __half2 h = __floats2half2_rn(x, y);
    return *reinterpret_cast<uint32_t*>(&h);
}

// ---------------------------------------------------------------------------
// fp16 NT GEMM chunk kernel (R10's proven 128x128 tile, 256 thr, warp 64x32).
// mode 0: grid (8,6): y<4 -> D-tile y (dec, +bias); y>=4 -> E-tile rows (y-4)*128
// mode 1: grid (8,2): E-tile rows eb*256 + y*128
// ---------------------------------------------------------------------------
__global__ void __launch_bounds__(256)
gemm_f16(const float* __restrict__ enc, const float* __restrict__ dec,
         const float* __restrict__ W, const float* __restrict__ bias,
         float* __restrict__ E, float* __restrict__ D, int mode, int eb)
{
    __shared__ uint32_t As[BK / 2][STR];
    __shared__ uint32_t Bs[BK / 2][STR];

    const int tid  = threadIdx.x;
    const int col0 = blockIdx.x * BN;
    bool isE;
    int row0;
    if (mode == 0) {
        isE  = (blockIdx.y >= 4);
        row0 = isE ? (blockIdx.y - 4) * BM : blockIdx.y * BM;
    } else {
        isE  = true;
        row0 = eb * 256 + blockIdx.y * BM;
    }
    const float* A = isE ? enc : dec;
    float* C       = isE ? E : D;

    const int arow = tid >> 1;
    const int kh   = (tid & 1) * 16;
    const int k2h  = (tid & 1) * 8;
    const float* aptr = A + (size_t)(row0 + arow) * KDIM + kh;
    const float* bptr = W + (size_t)(col0 + arow) * KDIM + kh;

    const int lane = tid & 31, warp = tid >> 5;
    const int g = lane >> 2, tig = lane & 3;
    const int wm = (warp >> 2) * 64, wn = (warp & 3) * 32;

    float acc[4][4][4];
#pragma unroll
    for (int mf = 0; mf < 4; mf++)
#pragma unroll
        for (int nf = 0; nf < 4; nf++)
#pragma unroll
            for (int i = 0; i < 4; i++) acc[mf][nf][i] = 0.f;

    float4 pa[4], pb[4];
#pragma unroll
    for (int j = 0; j < 4; j++) {
        pa[j] = *(const float4*)(aptr + j * 4);
        pb[j] = *(const float4*)(bptr + j * 4);
    }

    for (int kt = 0; kt < NKT; kt++) {
#pragma unroll
        for (int j = 0; j < 4; j++) {
            As[k2h + j * 2 + 0][arow] = pack_h2(pa[j].x, pa[j].y);
            As[k2h + j * 2 + 1][arow] = pack_h2(pa[j].z, pa[j].w);
            Bs[k2h + j * 2 + 0][arow] = pack_h2(pb[j].x, pb[j].y);
            Bs[k2h + j * 2 + 1][arow] = pack_h2(pb[j].z, pb[j].w);
        }
        __syncthreads();

        if (kt + 1 < NKT) {
            aptr += BK; bptr += BK;
#pragma unroll
            for (int j = 0; j < 4; j++) {
                pa[j] = *(const float4*)(aptr + j * 4);
                pb[j] = *(const float4*)(bptr + j * 4);
            }
        }

#pragma unroll
        for (int ks = 0; ks < 2; ks++) {
            const int k8 = ks * 8;
            uint32_t af[4][4], bf[4][2];
#pragma unroll
            for (int mf = 0; mf < 4; mf++) {
                const int m = wm + mf * 16 + g;
                af[mf][0] = As[k8 + tig][m];
                af[mf][1] = As[k8 + tig][m + 8];
                af[mf][2] = As[k8 + tig + 4][m];
                af[mf][3] = As[k8 + tig + 4][m + 8];
            }
#pragma unroll
            for (int nf = 0; nf < 4; nf++) {
                const int n = wn + nf * 8 + g;
                bf[nf][0] = Bs[k8 + tig][n];
                bf[nf][1] = Bs[k8 + tig + 4][n];
            }
#pragma unroll
            for (int mf = 0; mf < 4; mf++)
#pragma unroll
                for (int nf = 0; nf < 4; nf++)
                    mma_f16(acc[mf][nf], af[mf], bf[nf]);
        }
        __syncthreads();
    }

    float2 bv[4];
#pragma unroll
    for (int nf = 0; nf < 4; nf++) {
        if (isE) bv[nf] = make_float2(0.f, 0.f);
        else     bv[nf] = *(const float2*)(bias + col0 + wn + nf * 8 + tig * 2);
    }
#pragma unroll
    for (int mf = 0; mf < 4; mf++) {
        const int r = row0 + wm + mf * 16 + g;
#pragma unroll
        for (int nf = 0; nf < 4; nf++) {
            const int c = col0 + wn + nf * 8 + tig * 2;
            float2 v0 = make_float2(acc[mf][nf][0] + bv[nf].x,
                                    acc[mf][nf][1] + bv[nf].y);
            float2 v1 = make_float2(acc[mf][nf][2] + bv[nf].x,
                                    acc[mf][nf][3] + bv[nf].y);
            *(float2*)(C + (size_t)r * NDIM + c)       = v0;
            *(float2*)(C + (size_t)(r + 8) * NDIM + c) = v1;
        }
    }
}

// ---------------------------------------------------------------------------
// Per-batch broadcast add: out[b,t,u,v] = E[b*256+t, v] + D[b*64+u, v]
// grid 1024 = (t 0..255) x (u-slice 0..3 of 16 u each): one chunk alone fills
// the chip (~55 resident warps), matching R8's measured 5.5 TB/s.
// ---------------------------------------------------------------------------
__global__ void __launch_bounds__(256)
bcast_b(const float* __restrict__ E, const float* __restrict__ D,
        float* __restrict__ out, int b)
{
    const int bid = blockIdx.x;             // 0..1023
    const int t   = bid & 255;
    const int u0  = (bid >> 8) * 16;        // 0,16,32,48
    const int v4  = threadIdx.x;

    const float4* E4 = (const float4*)E;
    const float4* D4 = (const float4*)D;
    float4*       O4 = (float4*)out;

    const float4 e = E4[(size_t)(b * 256 + t) * 256 + v4];
    const size_t base = ((size_t)(b * 256 + t) * 64) * 256 + v4;
    const float4* Dp  = D4 + (size_t)(b * 64) * 256 + v4;

#pragma unroll
    for (int uu = 0; uu < 16; uu += 4) {
        const int u = u0 + uu;
        float4 d0 = __ldg(Dp + (size_t)(u + 0) * 256);
        float4 d1 = __ldg(Dp + (size_t)(u + 1) * 256);
        float4 d2 = __ldg(Dp + (size_t)(u + 2) * 256);
        float4 d3 = __ldg(Dp + (size_t)(u + 3) * 256);

        const size_t o = base + (size_t)u * 256;
        O4[o]           = make_float4(e.x + d0.x, e.y + d0.y, e.z + d0.z, e.w + d0.w);
        O4[o + 256]     = make_float4(e.x + d1.x, e.y + d1.y, e.z + d1.z, e.w + d1.w);
        O4[o + 2 * 256] = make_float4(e.x + d2.x, e.y + d2.y, e.z + d2.z, e.w + d2.w);
        O4[o + 3 * 256] = make_float4(e.x + d3.x, e.y + d3.y, e.z + d3.z, e.w + d3.w);
    }
}

// ---------------------------------------------------------------------------
// Pipelined schedule: GEMM chunks on the captured (legacy) stream, bcast
// chunks on a side stream, fork/join via events (capture-legal pattern).
// Falls back to the proven serial schedule if stream/event creation fails.
// ---------------------------------------------------------------------------
static cudaStream_t s_bc = nullptr;
static cudaEvent_t  s_ev[8], s_join;
static int s_state = 0;   // 0 = uninit, 1 = overlap ok, -1 = fallback

extern "C" void kernel_launch(void* const* d_in, const int* in_sizes, int n_in,
                              void* d_out, int out_size) {
    const float* enc  = (const float*)d_in[0];  // (8,256,512)
    const float* dec  = (const float*)d_in[1];  // (8,64,512)
    const float* W    = (const float*)d_in[2];  // (1024,512)
    const float* bias = (const float*)d_in[3];  // (1024,)
    float* out = (float*)d_out;                 // (8,256,64,1024)

    float *E, *D;
    cudaGetSymbolAddress((void**)&E, g_E);
    cudaGetSymbolAddress((void**)&D, g_D);

    if (s_state == 0) {
        s_state = 1;
        if (cudaStreamCreateWithFlags(&s_bc, cudaStreamNonBlocking) != cudaSuccess)
            s_state = -1;
        for (int i = 0; i < 8 && s_state == 1; i++)
            if (cudaEventCreateWithFlags(&s_ev[i], cudaEventDisableTiming) != cudaSuccess)
                s_state = -1;
        if (s_state == 1 &&
            cudaEventCreateWithFlags(&s_join, cudaEventDisableTiming) != cudaSuccess)
            s_state = -1;
    }

    if (s_state == 1) {
        // G_pre: all of D + E(batch 0), then fork bcast(0)
        gemm_f16<<<dim3(8, 6), 256>>>(enc, dec, W, bias, E, D, 0, 0);
        cudaEventRecord(s_ev[0], 0);
        cudaStreamWaitEvent(s_bc, s_ev[0], 0);
        bcast_b<<<1024, 256, 0, s_bc>>>(E, D, out, 0);

        for (int b = 1; b < 8; b++) {
            gemm_f16<<<dim3(8, 2), 256>>>(enc, dec, W, bias, E, D, 1, b);
            cudaEventRecord(s_ev[b], 0);
            cudaStreamWaitEvent(s_bc, s_ev[b], 0);
            bcast_b<<<1024, 256, 0, s_bc>>>(E, D, out, b);
        }
        cudaEventRecord(s_join, s_bc);
        cudaStreamWaitEvent(0, s_join, 0);
    } else {
        // Fallback: serial (R10 schedule, 125.5us)
        gemm_f16<<<dim3(8, 6), 256>>>(enc, dec, W, bias, E, D, 0, 0);
        for (int b = 1; b < 8; b++)
            gemm_f16<<<dim3(8, 2), 256>>>(enc, dec, W, bias, E, D, 1, b);
        for (int b = 0; b < 8; b++)
            bcast_b<<<1024, 256>>>(E, D, out, b);
    }
}

// round 13
// speedup vs baseline: 2.8993x; 2.8993x over previous
#include <cuda_runtime.h>
#include <cuda_fp16.h>
#include <cstdint>
#include <cstddef>

// Scratch: E = enc@W^T (2048x1024), D = dec@W^T + bias (512x1024)
__device__ float g_E[2048 * 1024];
__device__ float g_D[512 * 1024];

constexpr int KDIM = 512, NDIM = 1024;
constexpr int BM = 128, BN = 128, BK = 32;   // BK floats; 16 half2 k-rows
constexpr int NKT = KDIM / BK;               // 16 k-tiles
constexpr int STR = 136;                     // frag reads bank-conflict-free

__device__ __forceinline__ void mma_f16(float* c, const uint32_t* a, const uint32_t* b) {
    asm volatile(
        "mma.sync.aligned.m16n8k16.row.col.f32.f16.f16.f32 "
        "{%0,%1,%2,%3}, {%4,%5,%6,%7}, {%8,%9}, {%0,%1,%2,%3};\n"
        : "+f"(c[0]), "+f"(c[1]), "+f"(c[2]), "+f"(c[3])
        : "r"(a[0]), "r"(a[1]), "r"(a[2]), "r"(a[3]), "r"(b[0]), "r"(b[1]));
}

__device__ __forceinline__ uint32_t pack_h2(float x, float y) {
    __half2 h = __floats2half2_rn(x, y);
    return *reinterpret_cast<uint32_t*>(&h);
}

// ---------------------------------------------------------------------------
// fp16 NT GEMM (R10's proven 128x128 tile, 256 thr, 8 warps, warp 64x32).
// Global tile index yidx = blockIdx.y + y0:
//   yidx 0..3  -> D row-tile yidx (dec, +bias)
//   yidx 4..19 -> E row-tile (yidx-4) (enc)
// ---------------------------------------------------------------------------
__global__ void __launch_bounds__(256)
gemm_f16(const float* __restrict__ enc, const float* __restrict__ dec,
         const float* __restrict__ W, const float* __restrict__ bias,
         float* __restrict__ E, float* __restrict__ D, int y0)
{
    __shared__ uint32_t As[BK / 2][STR];
    __shared__ uint32_t Bs[BK / 2][STR];

    const int tid  = threadIdx.x;
    const int col0 = blockIdx.x * BN;
    const int yidx = blockIdx.y + y0;
    const bool isE = (yidx >= 4);
    const int row0 = isE ? (yidx - 4) * BM : yidx * BM;
    const float* A = isE ? enc : dec;
    float* C       = isE ? E : D;

    const int arow = tid >> 1;
    const int kh   = (tid & 1) * 16;
    const int k2h  = (tid & 1) * 8;
    const float* aptr = A + (size_t)(row0 + arow) * KDIM + kh;
    const float* bptr = W + (size_t)(col0 + arow) * KDIM + kh;

    const int lane = tid & 31, warp = tid >> 5;
    const int g = lane >> 2, tig = lane & 3;
    const int wm = (warp >> 2) * 64, wn = (warp & 3) * 32;

    float acc[4][4][4];
#pragma unroll
    for (int mf = 0; mf < 4; mf++)
#pragma unroll
        for (int nf = 0; nf < 4; nf++)
#pragma unroll
            for (int i = 0; i < 4; i++) acc[mf][nf][i] = 0.f;

    float4 pa[4], pb[4];
#pragma unroll
    for (int j = 0; j < 4; j++) {
        pa[j] = *(const float4*)(aptr + j * 4);
        pb[j] = *(const float4*)(bptr + j * 4);
    }

    for (int kt = 0; kt < NKT; kt++) {
#pragma unroll
        for (int j = 0; j < 4; j++) {
            As[k2h + j * 2 + 0][arow] = pack_h2(pa[j].x, pa[j].y);
            As[k2h + j * 2 + 1][arow] = pack_h2(pa[j].z, pa[j].w);
            Bs[k2h + j * 2 + 0][arow] = pack_h2(pb[j].x, pb[j].y);
            Bs[k2h + j * 2 + 1][arow] = pack_h2(pb[j].z, pb[j].w);
        }
        __syncthreads();

        if (kt + 1 < NKT) {
            aptr += BK; bptr += BK;
#pragma unroll
            for (int j = 0; j < 4; j++) {
                pa[j] = *(const float4*)(aptr + j * 4);
                pb[j] = *(const float4*)(bptr + j * 4);
            }
        }

#pragma unroll
        for (int ks = 0; ks < 2; ks++) {
            const int k8 = ks * 8;
            uint32_t af[4][4], bf[4][2];
#pragma unroll
            for (int mf = 0; mf < 4; mf++) {
                const int m = wm + mf * 16 + g;
                af[mf][0] = As[k8 + tig][m];
                af[mf][1] = As[k8 + tig][m + 8];
                af[mf][2] = As[k8 + tig + 4][m];
                af[mf][3] = As[k8 + tig + 4][m + 8];
            }
#pragma unroll
            for (int nf = 0; nf < 4; nf++) {
                const int n = wn + nf * 8 + g;
                bf[nf][0] = Bs[k8 + tig][n];
                bf[nf][1] = Bs[k8 + tig + 4][n];
            }
#pragma unroll
            for (int mf = 0; mf < 4; mf++)
#pragma unroll
                for (int nf = 0; nf < 4; nf++)
                    mma_f16(acc[mf][nf], af[mf], bf[nf]);
        }
        __syncthreads();
    }

    float2 bv[4];
#pragma unroll
    for (int nf = 0; nf < 4; nf++) {
        if (isE) bv[nf] = make_float2(0.f, 0.f);
        else     bv[nf] = *(const float2*)(bias + col0 + wn + nf * 8 + tig * 2);
    }
#pragma unroll
    for (int mf = 0; mf < 4; mf++) {
        const int r = row0 + wm + mf * 16 + g;
#pragma unroll
        for (int nf = 0; nf < 4; nf++) {
            const int c = col0 + wn + nf * 8 + tig * 2;
            float2 v0 = make_float2(acc[mf][nf][0] + bv[nf].x,
                                    acc[mf][nf][1] + bv[nf].y);
            float2 v1 = make_float2(acc[mf][nf][2] + bv[nf].x,
                                    acc[mf][nf][3] + bv[nf].y);
            *(float2*)(C + (size_t)r * NDIM + c)       = v0;
            *(float2*)(C + (size_t)(r + 8) * NDIM + c) = v1;
        }
    }
}

// ---------------------------------------------------------------------------
// Range broadcast add (R8's proven per-block shape: 1 t-row, all 64 u):
// out[b,t,u,v] = E[b*256+t, v] + D[b*64+u, v],  b = b0 + blockIdx.x>>8.
// ---------------------------------------------------------------------------
__global__ void __launch_bounds__(256)
bcast_r(const float* __restrict__ E, const float* __restrict__ D,
        float* __restrict__ out, int b0)
{
    const int b  = b0 + (blockIdx.x >> 8);
    const int t  = blockIdx.x & 255;
    const int v4 = threadIdx.x;

    const float4* E4 = (const float4*)E;
    const float4* D4 = (const float4*)D;
    float4*       O4 = (float4*)out;

    const float4 e = E4[(size_t)(b * 256 + t) * 256 + v4];
    const size_t base = ((size_t)(b * 256 + t) * 64) * 256 + v4;
    const float4* Dp  = D4 + (size_t)(b * 64) * 256 + v4;

    for (int u = 0; u < 64; u += 4) {
        float4 d0 = __ldg(Dp + (size_t)(u + 0) * 256);
        float4 d1 = __ldg(Dp + (size_t)(u + 1) * 256);
        float4 d2 = __ldg(Dp + (size_t)(u + 2) * 256);
        float4 d3 = __ldg(Dp + (size_t)(u + 3) * 256);

        const size_t o = base + (size_t)u * 256;
        O4[o]           = make_float4(e.x + d0.x, e.y + d0.y, e.z + d0.z, e.w + d0.w);
        O4[o + 256]     = make_float4(e.x + d1.x, e.y + d1.y, e.z + d1.z, e.w + d1.w);
        O4[o + 2 * 256] = make_float4(e.x + d2.x, e.y + d2.y, e.z + d2.z, e.w + d2.w);
        O4[o + 3 * 256] = make_float4(e.x + d3.x, e.y + d3.y, e.z + d3.z, e.w + d3.w);
    }
}

// ---------------------------------------------------------------------------
// 2+2 pipelined schedule (few, chip-filling chunks — R12 lesson):
//   stream0: gemmA (D + E b0,b1; 64 CTAs) -> evA -> gemmB (E b2..7; 96 CTAs) -> evB
//   side:    wait evA -> bcastA (b0,b1; 512 blk); wait evB -> bcastB (b2..7; 1536 blk)
//   join back to stream0. Falls back to serial if setup fails.
// ---------------------------------------------------------------------------
static cudaStream_t s_bc = nullptr;
static cudaEvent_t  s_evA, s_evB, s_join;
static int s_state = 0;   // 0 uninit, 1 overlap, -1 fallback

extern "C" void kernel_launch(void* const* d_in, const int* in_sizes, int n_in,
                              void* d_out, int out_size) {
    const float* enc  = (const float*)d_in[0];  // (8,256,512)
    const float* dec  = (const float*)d_in[1];  // (8,64,512)
    const float* W    = (const float*)d_in[2];  // (1024,512)
    const float* bias = (const float*)d_in[3];  // (1024,)
    float* out = (float*)d_out;                 // (8,256,64,1024)

    float *E, *D;
    cudaGetSymbolAddress((void**)&E, g_E);
    cudaGetSymbolAddress((void**)&D, g_D);

    if (s_state == 0) {
        s_state = 1;
        if (cudaStreamCreateWithFlags(&s_bc, cudaStreamNonBlocking) != cudaSuccess)
            s_state = -1;
        if (s_state == 1 &&
            (cudaEventCreateWithFlags(&s_evA, cudaEventDisableTiming) != cudaSuccess ||
             cudaEventCreateWithFlags(&s_evB, cudaEventDisableTiming) != cudaSuccess ||
             cudaEventCreateWithFlags(&s_join, cudaEventDisableTiming) != cudaSuccess))
            s_state = -1;
    }

    if (s_state == 1) {
        // gemmA: yidx 0..7 = D tiles 0..3 + E tiles 0..3 (rows 0..511 = b0,b1)
        gemm_f16<<<dim3(8, 8), 256>>>(enc, dec, W, bias, E, D, 0);
        cudaEventRecord(s_evA, 0);
        // gemmB: yidx 8..19 = E tiles 4..15 (rows 512..2047 = b2..b7)
        gemm_f16<<<dim3(8, 12), 256>>>(enc, dec, W, bias, E, D, 8);
        cudaEventRecord(s_evB, 0);

        cudaStreamWaitEvent(s_bc, s_evA, 0);
        bcast_r<<<512, 256, 0, s_bc>>>(E, D, out, 0);    // b0,b1
        cudaStreamWaitEvent(s_bc, s_evB, 0);
        bcast_r<<<1536, 256, 0, s_bc>>>(E, D, out, 2);   // b2..b7

        cudaEventRecord(s_join, s_bc);
        cudaStreamWaitEvent(0, s_join, 0);
    } else {
        // Serial fallback (R10-equivalent schedule)
        gemm_f16<<<dim3(8, 8), 256>>>(enc, dec, W, bias, E, D, 0);
        gemm_f16<<<dim3(8, 12), 256>>>(enc, dec, W, bias, E, D, 8);
        bcast_r<<<512, 256>>>(E, D, out, 0);
        bcast_r<<<1536, 256>>>(E, D, out, 2);
    }
}

// round 14
// speedup vs baseline: 2.9375x; 1.0132x over previous
#include <cuda_runtime.h>
#include <cuda_fp16.h>
#include <cstdint>
#include <cstddef>

// Scratch: E = enc@W^T (2048x1024), D = dec@W^T + bias (512x1024)
__device__ float g_E[2048 * 1024];
__device__ float g_D[512 * 1024];

// fp16 copies of inputs: [enc | dec | W], converted once per launch
constexpr size_t ENC_N = 2048 * 512, DEC_N = 512 * 512, W_N = 1024 * 512;
__device__ __half g_H[ENC_N + DEC_N + W_N];

constexpr int KDIM = 512, NDIM = 1024;
constexpr int BM = 128, BN = 128;
constexpr int BK2 = 32;                 // half2 k-rows per tile (64 halves)
constexpr int NKT = KDIM / 64;          // 8 k-tiles
constexpr int STR = 136;                // frag reads bank-conflict-free

__device__ __forceinline__ void mma_f16(float* c, const uint32_t* a, const uint32_t* b) {
    asm volatile(
        "mma.sync.aligned.m16n8k16.row.col.f32.f16.f16.f32 "
        "{%0,%1,%2,%3}, {%4,%5,%6,%7}, {%8,%9}, {%0,%1,%2,%3};\n"
        : "+f"(c[0]), "+f"(c[1]), "+f"(c[2]), "+f"(c[3])
        : "r"(a[0]), "r"(a[1]), "r"(a[2]), "r"(a[3]), "r"(b[0]), "r"(b[1]));
}

__device__ __forceinline__ uint32_t pack_h2(float x, float y) {
    __half2 h = __floats2half2_rn(x, y);
    return *reinterpret_cast<uint32_t*>(&h);
}

// ---------------------------------------------------------------------------
// One-shot fp32 -> fp16 convert of all GEMM inputs. 8 floats per thread.
// Region sizes are multiples of 8, so no thread straddles a boundary.
// ---------------------------------------------------------------------------
__global__ void __launch_bounds__(256)
cvt_f16(const float* __restrict__ enc, const float* __restrict__ dec,
        const float* __restrict__ W)
{
    const size_t i = ((size_t)blockIdx.x * 256 + threadIdx.x) * 8;
    const float* src;
    size_t off;
    if (i < ENC_N)              { src = enc; off = i; }
    else if (i < ENC_N + DEC_N) { src = dec; off = i - ENC_N; }
    else                        { src = W;   off = i - ENC_N - DEC_N; }
    float4 a = *(const float4*)(src + off);
    float4 b = *(const float4*)(src + off + 4);
    uint4 o;
    o.x = pack_h2(a.x, a.y); o.y = pack_h2(a.z, a.w);
    o.z = pack_h2(b.x, b.y); o.w = pack_h2(b.z, b.w);
    *(uint4*)(&g_H[i]) = o;
}

// ---------------------------------------------------------------------------
// fp16-input NT GEMM: 128x128 tile, 256 thr, 8 warps (2x4), warp 64x32,
// BK=64 halves (8 k-tiles). Staging is pure LDG.128->STS (no cvt in loop).
// yidx = blockIdx.y + y0: 0..3 -> D row-tile (dec,+bias); 4..19 -> E row-tile.
// ---------------------------------------------------------------------------
__global__ void __launch_bounds__(256)
gemm_f16(const float* __restrict__ bias, float* __restrict__ E,
         float* __restrict__ D, int y0)
{
    __shared__ uint32_t As[BK2][STR];
    __shared__ uint32_t Bs[BK2][STR];

    const __half* encH = g_H;
    const __half* decH = g_H + ENC_N;
    const __half* WH   = g_H + ENC_N + DEC_N;

    const int tid  = threadIdx.x;
    const int col0 = blockIdx.x * BN;
    const int yidx = blockIdx.y + y0;
    const bool isE = (yidx >= 4);
    const int row0 = isE ? (yidx - 4) * BM : yidx * BM;
    const __half* A = isE ? encH : decH;
    float* C        = isE ? E : D;

    // Staging: 2 thr/row, each covers 32 halves (4 x LDG.128)
    const int arow = tid >> 1;
    const int hh   = (tid & 1) * 32;    // half offset within tile
    const int k2h  = (tid & 1) * 16;    // half2-row offset
    const __half* aptr = A  + (size_t)(row0 + arow) * KDIM + hh;
    const __half* bptr = WH + (size_t)(col0 + arow) * KDIM + hh;

    const int lane = tid & 31, warp = tid >> 5;
    const int g = lane >> 2, tig = lane & 3;
    const int wm = (warp >> 2) * 64, wn = (warp & 3) * 32;

    float acc[4][4][4];
#pragma unroll
    for (int mf = 0; mf < 4; mf++)
#pragma unroll
        for (int nf = 0; nf < 4; nf++)
#pragma unroll
            for (int i = 0; i < 4; i++) acc[mf][nf][i] = 0.f;

    uint4 pa[4], pb[4];
#pragma unroll
    for (int j = 0; j < 4; j++) {
        pa[j] = *(const uint4*)(aptr + j * 8);
        pb[j] = *(const uint4*)(bptr + j * 8);
    }

    for (int kt = 0; kt < NKT; kt++) {
        // stage prefetched tile (each uint4 = 4 half2 at consecutive k2 rows)
#pragma unroll
        for (int j = 0; j < 4; j++) {
            As[k2h + j * 4 + 0][arow] = pa[j].x;
            As[k2h + j * 4 + 1][arow] = pa[j].y;
            As[k2h + j * 4 + 2][arow] = pa[j].z;
            As[k2h + j * 4 + 3][arow] = pa[j].w;
            Bs[k2h + j * 4 + 0][arow] = pb[j].x;
            Bs[k2h + j * 4 + 1][arow] = pb[j].y;
            Bs[k2h + j * 4 + 2][arow] = pb[j].z;
            Bs[k2h + j * 4 + 3][arow] = pb[j].w;
        }
        __syncthreads();

        if (kt + 1 < NKT) {             // prefetch next tile
            aptr += 64; bptr += 64;
#pragma unroll
            for (int j = 0; j < 4; j++) {
                pa[j] = *(const uint4*)(aptr + j * 8);
                pb[j] = *(const uint4*)(bptr + j * 8);
            }
        }

        // 4 k16-steps per tile
#pragma unroll
        for (int ks = 0; ks < 4; ks++) {
            const int k8 = ks * 8;
            uint32_t af[4][4], bf[4][2];
#pragma unroll
            for (int mf = 0; mf < 4; mf++) {
                const int m = wm + mf * 16 + g;
                af[mf][0] = As[k8 + tig][m];
                af[mf][1] = As[k8 + tig][m + 8];
                af[mf][2] = As[k8 + tig + 4][m];
                af[mf][3] = As[k8 + tig + 4][m + 8];
            }
#pragma unroll
            for (int nf = 0; nf < 4; nf++) {
                const int n = wn + nf * 8 + g;
                bf[nf][0] = Bs[k8 + tig][n];
                bf[nf][1] = Bs[k8 + tig + 4][n];
            }
#pragma unroll
            for (int mf = 0; mf < 4; mf++)
#pragma unroll
                for (int nf = 0; nf < 4; nf++)
                    mma_f16(acc[mf][nf], af[mf], bf[nf]);
        }
        __syncthreads();
    }

    float2 bv[4];
#pragma unroll
    for (int nf = 0; nf < 4; nf++) {
        if (isE) bv[nf] = make_float2(0.f, 0.f);
        else     bv[nf] = *(const float2*)(bias + col0 + wn + nf * 8 + tig * 2);
    }
#pragma unroll
    for (int mf = 0; mf < 4; mf++) {
        const int r = row0 + wm + mf * 16 + g;
#pragma unroll
        for (int nf = 0; nf < 4; nf++) {
            const int c = col0 + wn + nf * 8 + tig * 2;
            float2 v0 = make_float2(acc[mf][nf][0] + bv[nf].x,
                                    acc[mf][nf][1] + bv[nf].y);
            float2 v1 = make_float2(acc[mf][nf][2] + bv[nf].x,
                                    acc[mf][nf][3] + bv[nf].y);
            *(float2*)(C + (size_t)r * NDIM + c)       = v0;
            *(float2*)(C + (size_t)(r + 8) * NDIM + c) = v1;
        }
    }
}

// ---------------------------------------------------------------------------
// Range broadcast add (R13, measured 5.4 TB/s):
// out[b,t,u,v] = E[b*256+t, v] + D[b*64+u, v],  b = b0 + blockIdx.x>>8.
// ---------------------------------------------------------------------------
__global__ void __launch_bounds__(256)
bcast_r(const float* __restrict__ E, const float* __restrict__ D,
        float* __restrict__ out, int b0)
{
    const int b  = b0 + (blockIdx.x >> 8);
    const int t  = blockIdx.x & 255;
    const int v4 = threadIdx.x;

    const float4* E4 = (const float4*)E;
    const float4* D4 = (const float4*)D;
    float4*       O4 = (float4*)out;

    const float4 e = E4[(size_t)(b * 256 + t) * 256 + v4];
    const size_t base = ((size_t)(b * 256 + t) * 64) * 256 + v4;
    const float4* Dp  = D4 + (size_t)(b * 64) * 256 + v4;

    for (int u = 0; u < 64; u += 4) {
        float4 d0 = __ldg(Dp + (size_t)(u + 0) * 256);
        float4 d1 = __ldg(Dp + (size_t)(u + 1) * 256);
        float4 d2 = __ldg(Dp + (size_t)(u + 2) * 256);
        float4 d3 = __ldg(Dp + (size_t)(u + 3) * 256);

        const size_t o = base + (size_t)u * 256;
        O4[o]           = make_float4(e.x + d0.x, e.y + d0.y, e.z + d0.z, e.w + d0.w);
        O4[o + 256]     = make_float4(e.x + d1.x, e.y + d1.y, e.z + d1.z, e.w + d1.w);
        O4[o + 2 * 256] = make_float4(e.x + d2.x, e.y + d2.y, e.z + d2.z, e.w + d2.w);
        O4[o + 3 * 256] = make_float4(e.x + d3.x, e.y + d3.y, e.z + d3.z, e.w + d3.w);
    }
}

// ---------------------------------------------------------------------------
// Schedule (R13's proven 2+2 overlap, plus cvt prologue):
//   stream0: cvt -> gemmA (D + E b0,b1) -> evA -> gemmB (E b2..7) -> evB
//   side:    wait evA -> bcastA (b0,b1); wait evB -> bcastB (b2..7); join.
// ---------------------------------------------------------------------------
static cudaStream_t s_bc = nullptr;
static cudaEvent_t  s_evA, s_evB, s_join;
static int s_state = 0;

extern "C" void kernel_launch(void* const* d_in, const int* in_sizes, int n_in,
                              void* d_out, int out_size) {
    const float* enc  = (const float*)d_in[0];  // (8,256,512)
    const float* dec  = (const float*)d_in[1];  // (8,64,512)
    const float* W    = (const float*)d_in[2];  // (1024,512)
    const float* bias = (const float*)d_in[3];  // (1024,)
    float* out = (float*)d_out;                 // (8,256,64,1024)

    float *E, *D;
    cudaGetSymbolAddress((void**)&E, g_E);
    cudaGetSymbolAddress((void**)&D, g_D);

    if (s_state == 0) {
        s_state = 1;
        if (cudaStreamCreateWithFlags(&s_bc, cudaStreamNonBlocking) != cudaSuccess)
            s_state = -1;
        if (s_state == 1 &&
            (cudaEventCreateWithFlags(&s_evA, cudaEventDisableTiming) != cudaSuccess ||
             cudaEventCreateWithFlags(&s_evB, cudaEventDisableTiming) != cudaSuccess ||
             cudaEventCreateWithFlags(&s_join, cudaEventDisableTiming) != cudaSuccess))
            s_state = -1;
    }

    const int cvt_blocks = (int)((ENC_N + DEC_N + W_N) / 8 / 256);  // 896

    if (s_state == 1) {
        cvt_f16<<<cvt_blocks, 256>>>(enc, dec, W);
        // gemmA: yidx 0..7 = D tiles 0..3 + E tiles 0..3 (rows = b0,b1)
        gemm_f16<<<dim3(8, 8), 256>>>(bias, E, D, 0);
        cudaEventRecord(s_evA, 0);
        // gemmB: yidx 8..19 = E tiles 4..15 (b2..b7)
        gemm_f16<<<dim3(8, 12), 256>>>(bias, E, D, 8);
        cudaEventRecord(s_evB, 0);

        cudaStreamWaitEvent(s_bc, s_evA, 0);
        bcast_r<<<512, 256, 0, s_bc>>>(E, D, out, 0);    // b0,b1
        cudaStreamWaitEvent(s_bc, s_evB, 0);
        bcast_r<<<1536, 256, 0, s_bc>>>(E, D, out, 2);   // b2..b7

        cudaEventRecord(s_join, s_bc);
        cudaStreamWaitEvent(0, s_join, 0);
    } else {
        cvt_f16<<<cvt_blocks, 256>>>(enc, dec, W);
        gemm_f16<<<dim3(8, 8), 256>>>(bias, E, D, 0);
        gemm_f16<<<dim3(8, 12), 256>>>(bias, E, D, 8);
        bcast_r<<<512, 256>>>(E, D, out, 0);
        bcast_r<<<1536, 256>>>(E, D, out, 2);
    }
}

// round 15
// speedup vs baseline: 3.2685x; 1.1127x over previous
#include <cuda_runtime.h>
#include <cuda_fp16.h>
#include <cstdint>
#include <cstddef>

// Scratch: E = enc@W^T (2048x1024), D = dec@W^T + bias (512x1024)
__device__ float g_E[2048 * 1024];
__device__ float g_D[512 * 1024];

// fp16 copies of inputs: [enc | dec | W], converted once per launch
constexpr size_t ENC_N = 2048 * 512, DEC_N = 512 * 512, W_N = 1024 * 512;
__device__ __half g_H[ENC_N + DEC_N + W_N];

constexpr int KDIM = 512, NDIM = 1024;
constexpr int BM = 128, BN = 128;
constexpr int BK2 = 32;                 // half2 k-rows per tile (64 halves)
constexpr int NKT = KDIM / 64;          // 8 k-tiles
constexpr int STR = 136;                // frag reads bank-conflict-free

__device__ __forceinline__ void mma_f16(float* c, const uint32_t* a, const uint32_t* b) {
    asm volatile(
        "mma.sync.aligned.m16n8k16.row.col.f32.f16.f16.f32 "
        "{%0,%1,%2,%3}, {%4,%5,%6,%7}, {%8,%9}, {%0,%1,%2,%3};\n"
        : "+f"(c[0]), "+f"(c[1]), "+f"(c[2]), "+f"(c[3])
        : "r"(a[0]), "r"(a[1]), "r"(a[2]), "r"(a[3]), "r"(b[0]), "r"(b[1]));
}

__device__ __forceinline__ uint32_t pack_h2(float x, float y) {
    __half2 h = __floats2half2_rn(x, y);
    return *reinterpret_cast<uint32_t*>(&h);
}

// ---------------------------------------------------------------------------
// One-shot fp32 -> fp16 convert of all GEMM inputs. 8 floats per thread.
// ---------------------------------------------------------------------------
__global__ void __launch_bounds__(256)
cvt_f16(const float* __restrict__ enc, const float* __restrict__ dec,
        const float* __restrict__ W)
{
    const size_t i = ((size_t)blockIdx.x * 256 + threadIdx.x) * 8;
    const float* src;
    size_t off;
    if (i < ENC_N)              { src = enc; off = i; }
    else if (i < ENC_N + DEC_N) { src = dec; off = i - ENC_N; }
    else                        { src = W;   off = i - ENC_N - DEC_N; }
    float4 a = *(const float4*)(src + off);
    float4 b = *(const float4*)(src + off + 4);
    uint4 o;
    o.x = pack_h2(a.x, a.y); o.y = pack_h2(a.z, a.w);
    o.z = pack_h2(b.x, b.y); o.w = pack_h2(b.z, b.w);
    *(uint4*)(&g_H[i]) = o;
}

// ---------------------------------------------------------------------------
// fp16-input NT GEMM (R14): 128x128 tile, 256 thr, warp 64x32, BK=64 halves.
// yidx = blockIdx.y + y0: 0..3 -> D row-tile (dec,+bias); 4..19 -> E row-tile.
// ---------------------------------------------------------------------------
__global__ void __launch_bounds__(256)
gemm_f16(const float* __restrict__ bias, float* __restrict__ E,
         float* __restrict__ D, int y0)
{
    __shared__ uint32_t As[BK2][STR];
    __shared__ uint32_t Bs[BK2][STR];

    const __half* encH = g_H;
    const __half* decH = g_H + ENC_N;
    const __half* WH   = g_H + ENC_N + DEC_N;

    const int tid  = threadIdx.x;
    const int col0 = blockIdx.x * BN;
    const int yidx = blockIdx.y + y0;
    const bool isE = (yidx >= 4);
    const int row0 = isE ? (yidx - 4) * BM : yidx * BM;
    const __half* A = isE ? encH : decH;
    float* C        = isE ? E : D;

    const int arow = tid >> 1;
    const int hh   = (tid & 1) * 32;
    const int k2h  = (tid & 1) * 16;
    const __half* aptr = A  + (size_t)(row0 + arow) * KDIM + hh;
    const __half* bptr = WH + (size_t)(col0 + arow) * KDIM + hh;

    const int lane = tid & 31, warp = tid >> 5;
    const int g = lane >> 2, tig = lane & 3;
    const int wm = (warp >> 2) * 64, wn = (warp & 3) * 32;

    float acc[4][4][4];
#pragma unroll
    for (int mf = 0; mf < 4; mf++)
#pragma unroll
        for (int nf = 0; nf < 4; nf++)
#pragma unroll
            for (int i = 0; i < 4; i++) acc[mf][nf][i] = 0.f;

    uint4 pa[4], pb[4];
#pragma unroll
    for (int j = 0; j < 4; j++) {
        pa[j] = *(const uint4*)(aptr + j * 8);
        pb[j] = *(const uint4*)(bptr + j * 8);
    }

    for (int kt = 0; kt < NKT; kt++) {
#pragma unroll
        for (int j = 0; j < 4; j++) {
            As[k2h + j * 4 + 0][arow] = pa[j].x;
            As[k2h + j * 4 + 1][arow] = pa[j].y;
            As[k2h + j * 4 + 2][arow] = pa[j].z;
            As[k2h + j * 4 + 3][arow] = pa[j].w;
            Bs[k2h + j * 4 + 0][arow] = pb[j].x;
            Bs[k2h + j * 4 + 1][arow] = pb[j].y;
            Bs[k2h + j * 4 + 2][arow] = pb[j].z;
            Bs[k2h + j * 4 + 3][arow] = pb[j].w;
        }
        __syncthreads();

        if (kt + 1 < NKT) {
            aptr += 64; bptr += 64;
#pragma unroll
            for (int j = 0; j < 4; j++) {
                pa[j] = *(const uint4*)(aptr + j * 8);
                pb[j] = *(const uint4*)(bptr + j * 8);
            }
        }

#pragma unroll
        for (int ks = 0; ks < 4; ks++) {
            const int k8 = ks * 8;
            uint32_t af[4][4], bf[4][2];
#pragma unroll
            for (int mf = 0; mf < 4; mf++) {
                const int m = wm + mf * 16 + g;
                af[mf][0] = As[k8 + tig][m];
                af[mf][1] = As[k8 + tig][m + 8];
                af[mf][2] = As[k8 + tig + 4][m];
                af[mf][3] = As[k8 + tig + 4][m + 8];
            }
#pragma unroll
            for (int nf = 0; nf < 4; nf++) {
                const int n = wn + nf * 8 + g;
                bf[nf][0] = Bs[k8 + tig][n];
                bf[nf][1] = Bs[k8 + tig + 4][n];
            }
#pragma unroll
            for (int mf = 0; mf < 4; mf++)
#pragma unroll
                for (int nf = 0; nf < 4; nf++)
                    mma_f16(acc[mf][nf], af[mf], bf[nf]);
        }
        __syncthreads();
    }

    float2 bv[4];
#pragma unroll
    for (int nf = 0; nf < 4; nf++) {
        if (isE) bv[nf] = make_float2(0.f, 0.f);
        else     bv[nf] = *(const float2*)(bias + col0 + wn + nf * 8 + tig * 2);
    }
#pragma unroll
    for (int mf = 0; mf < 4; mf++) {
        const int r = row0 + wm + mf * 16 + g;
#pragma unroll
        for (int nf = 0; nf < 4; nf++) {
            const int c = col0 + wn + nf * 8 + tig * 2;
            float2 v0 = make_float2(acc[mf][nf][0] + bv[nf].x,
                                    acc[mf][nf][1] + bv[nf].y);
            float2 v1 = make_float2(acc[mf][nf][2] + bv[nf].x,
                                    acc[mf][nf][3] + bv[nf].y);
            *(float2*)(C + (size_t)r * NDIM + c)       = v0;
            *(float2*)(C + (size_t)(r + 8) * NDIM + c) = v1;
        }
    }
}

// ---------------------------------------------------------------------------
// Range broadcast add with u-split:
// grid = nb * 256 * US blocks; block handles (b, t) and 64/US u-rows.
// Streaming stores: output is write-once, keep L2 for D/E + gemm traffic.
// ---------------------------------------------------------------------------
template <int US>
__global__ void __launch_bounds__(256)
bcast_r(const float* __restrict__ E, const float* __restrict__ D,
        float* __restrict__ out, int b0)
{
    const int t    = blockIdx.x & 255;
    const int rest = blockIdx.x >> 8;
    const int b    = b0 + rest / US;
    const int u0   = (rest % US) * (64 / US);
    const int v4   = threadIdx.x;

    const float4* E4 = (const float4*)E;
    const float4* D4 = (const float4*)D;
    float4*       O4 = (float4*)out;

    const float4 e = E4[(size_t)(b * 256 + t) * 256 + v4];
    const size_t base = ((size_t)(b * 256 + t) * 64) * 256 + v4;
    const float4* Dp  = D4 + (size_t)(b * 64) * 256 + v4;

    for (int u = u0; u < u0 + 64 / US; u += 4) {
        float4 d0 = __ldg(Dp + (size_t)(u + 0) * 256);
        float4 d1 = __ldg(Dp + (size_t)(u + 1) * 256);
        float4 d2 = __ldg(Dp + (size_t)(u + 2) * 256);
        float4 d3 = __ldg(Dp + (size_t)(u + 3) * 256);

        const size_t o = base + (size_t)u * 256;
        __stcs(O4 + o,
               make_float4(e.x + d0.x, e.y + d0.y, e.z + d0.z, e.w + d0.w));
        __stcs(O4 + o + 256,
               make_float4(e.x + d1.x, e.y + d1.y, e.z + d1.z, e.w + d1.w));
        __stcs(O4 + o + 2 * 256,
               make_float4(e.x + d2.x, e.y + d2.y, e.z + d2.z, e.w + d2.w));
        __stcs(O4 + o + 3 * 256,
               make_float4(e.x + d3.x, e.y + d3.y, e.z + d3.z, e.w + d3.w));
    }
}

// ---------------------------------------------------------------------------
// Schedule (R13/14 proven 2+2 overlap + cvt prologue):
//   stream0: cvt -> gemmA (D + E b0,b1) -> evA -> gemmB (E b2..7) -> evB
//   side:    wait evA -> bcastA (b0,b1; u-split x2, 1024 blk)
//            wait evB -> bcastB (b2..7; 1536 blk); join.
// ---------------------------------------------------------------------------
static cudaStream_t s_bc = nullptr;
static cudaEvent_t  s_evA, s_evB, s_join;
static int s_state = 0;

extern "C" void kernel_launch(void* const* d_in, const int* in_sizes, int n_in,
                              void* d_out, int out_size) {
    const float* enc  = (const float*)d_in[0];  // (8,256,512)
    const float* dec  = (const float*)d_in[1];  // (8,64,512)
    const float* W    = (const float*)d_in[2];  // (1024,512)
    const float* bias = (const float*)d_in[3];  // (1024,)
    float* out = (float*)d_out;                 // (8,256,64,1024)

    float *E, *D;
    cudaGetSymbolAddress((void**)&E, g_E);
    cudaGetSymbolAddress((void**)&D, g_D);

    if (s_state == 0) {
        s_state = 1;
        if (cudaStreamCreateWithFlags(&s_bc, cudaStreamNonBlocking) != cudaSuccess)
            s_state = -1;
        if (s_state == 1 &&
            (cudaEventCreateWithFlags(&s_evA, cudaEventDisableTiming) != cudaSuccess ||
             cudaEventCreateWithFlags(&s_evB, cudaEventDisableTiming) != cudaSuccess ||
             cudaEventCreateWithFlags(&s_join, cudaEventDisableTiming) != cudaSuccess))
            s_state = -1;
    }

    const int cvt_blocks = (int)((ENC_N + DEC_N + W_N) / 8 / 256);  // 896

    if (s_state == 1) {
        cvt_f16<<<cvt_blocks, 256>>>(enc, dec, W);
        gemm_f16<<<dim3(8, 8), 256>>>(bias, E, D, 0);    // D + E(b0,b1)
        cudaEventRecord(s_evA, 0);
        gemm_f16<<<dim3(8, 12), 256>>>(bias, E, D, 8);   // E(b2..b7)
        cudaEventRecord(s_evB, 0);

        cudaStreamWaitEvent(s_bc, s_evA, 0);
        bcast_r<2><<<1024, 256, 0, s_bc>>>(E, D, out, 0);   // b0,b1 u-split x2
        cudaStreamWaitEvent(s_bc, s_evB, 0);
        bcast_r<1><<<1536, 256, 0, s_bc>>>(E, D, out, 2);   // b2..b7

        cudaEventRecord(s_join, s_bc);
        cudaStreamWaitEvent(0, s_join, 0);
    } else {
        cvt_f16<<<cvt_blocks, 256>>>(enc, dec, W);
        gemm_f16<<<dim3(8, 8), 256>>>(bias, E, D, 0);
        gemm_f16<<<dim3(8, 12), 256>>>(bias, E, D, 8);
        bcast_r<2><<<1024, 256>>>(E, D, out, 0);
        bcast_r<1><<<1536, 256>>>(E, D, out, 2);
    }
}